// round 15
// baseline (speedup 1.0000x reference)
#include <cuda_runtime.h>
#include <cuda_bf16.h>
#include <cstdint>

using bf16  = __nv_bfloat16;

#define DEV __device__ __forceinline__

#if defined(__CUDA_ARCH_FEAT_SM103_ALL) || defined(__CUDA_ARCH_FEAT_SM100_ALL) || defined(__CUDA_ARCH_FEAT_SM101_ALL)
#define HAS_TC 1
#else
#define HAS_TC 0
#endif

static constexpr int BATCH = 8;
static constexpr int C     = 256;
static constexpr int NTOK  = 4096;
static constexpr int GRP   = 32;
static constexpr int CPG   = C / GRP;

// ---------------- static device scratch ----------------
__device__ float g_stats[BATCH * GRP * 2];
__device__ bf16  g_xn  [(size_t)BATCH * NTOK * C];
__device__ bf16  g_wqk [512 * 256];
__device__ bf16  g_wv  [256 * 256];
__device__ bf16  g_wo  [256 * 256];
__device__ float g_bqk [512];
__device__ float g_bv  [256];
__device__ bf16  g_qk  [(size_t)BATCH * NTOK * 512];
__device__ bf16  g_v   [(size_t)BATCH * 256 * NTOK];
__device__ bf16  g_attn[(size_t)BATCH * NTOK * 256];

// ---------------- helpers ----------------
DEV float warp_sum(float v) {
    #pragma unroll
    for (int o = 16; o; o >>= 1) v += __shfl_xor_sync(0xffffffffu, v, o);
    return v;
}
DEV unsigned smem_u32(const void *p) { return (unsigned)__cvta_generic_to_shared(p); }

DEV void cp16(unsigned dst_smem, const bf16 *src) {
    asm volatile("cp.async.cg.shared.global [%0], [%1], 16;\n" :: "r"(dst_smem), "l"(src));
}
DEV void cp_commit() { asm volatile("cp.async.commit_group;\n"); }
template <int N> DEV void cp_wait() { asm volatile("cp.async.wait_group %0;\n" :: "n"(N)); }

DEV unsigned pack_bf16x2(float lo, float hi) {
    unsigned r;
    asm("cvt.rn.bf16x2.f32 %0, %1, %2;" : "=r"(r) : "f"(hi), "f"(lo));
    return r;
}

// ---- mma.sync fallback primitives ----
DEV void ldsm_x4(unsigned &r0, unsigned &r1, unsigned &r2, unsigned &r3, unsigned addr) {
    asm volatile("ldmatrix.sync.aligned.m8n8.x4.shared.b16 {%0,%1,%2,%3}, [%4];"
                 : "=r"(r0), "=r"(r1), "=r"(r2), "=r"(r3) : "r"(addr));
}
DEV void mma16816(float *d, const unsigned *a, const unsigned *b) {
    asm volatile("mma.sync.aligned.m16n8k16.row.col.f32.bf16.bf16.f32 "
                 "{%0,%1,%2,%3}, {%4,%5,%6,%7}, {%8,%9}, {%0,%1,%2,%3};"
                 : "+f"(d[0]), "+f"(d[1]), "+f"(d[2]), "+f"(d[3])
                 : "r"(a[0]), "r"(a[1]), "r"(a[2]), "r"(a[3]), "r"(b[0]), "r"(b[1]));
}

// ---- tcgen05 primitives ----
#define SW128_SWZ(off) ((off) ^ (((off) >> 3) & 0x70))
static constexpr uint64_t DESC_BASE =
    (uint64_t(2) << 61) | (uint64_t(1) << 46) | (uint64_t(64) << 32) | (uint64_t(1) << 16);
DEV uint64_t mkdesc(unsigned smem_addr) { return DESC_BASE | ((smem_addr >> 4) & 0x3FFF); }

#if HAS_TC
DEV void tc_alloc(unsigned smem_dst, unsigned ncols) {
    asm volatile("tcgen05.alloc.cta_group::1.sync.aligned.shared::cta.b32 [%0], %1;"
                 :: "r"(smem_dst), "r"(ncols) : "memory");
}
DEV void tc_dealloc(unsigned tmem, unsigned ncols) {
    asm volatile("tcgen05.dealloc.cta_group::1.sync.aligned.b32 %0, %1;" :: "r"(tmem), "r"(ncols));
}
DEV void tc_relinq() {
    asm volatile("tcgen05.relinquish_alloc_permit.cta_group::1.sync.aligned;");
}
DEV void tc_mma_f16_ss(unsigned d, uint64_t ad, uint64_t bd, unsigned idesc, unsigned en) {
    asm volatile("{\n\t.reg .pred p;\n\tsetp.ne.u32 p, %5, 0;\n\t"
                 "tcgen05.mma.cta_group::1.kind::f16 [%0], %1, %2, %3, {%4, %4, %4, %4}, p;\n\t}"
                 :: "r"(d), "l"(ad), "l"(bd), "r"(idesc), "r"(0u), "r"(en) : "memory");
}
DEV void tc_commit(unsigned mbar) {
    asm volatile("tcgen05.commit.cta_group::1.mbarrier::arrive::one.shared::cluster.b64 [%0];"
                 :: "r"(mbar) : "memory");
}
DEV void tc_fence_after() { asm volatile("tcgen05.fence::after_thread_sync;" ::: "memory"); }
DEV void tc_fence_before() { asm volatile("tcgen05.fence::before_thread_sync;" ::: "memory"); }
DEV void tc_wait_ld() { asm volatile("tcgen05.wait::ld.sync.aligned;" ::: "memory"); }
DEV void fence_proxy_async_cta() { asm volatile("fence.proxy.async.shared::cta;" ::: "memory"); }
DEV void mbar_init(unsigned mbar, unsigned cnt) {
    asm volatile("mbarrier.init.shared.b64 [%0], %1;" :: "r"(mbar), "r"(cnt) : "memory");
}
DEV void mbar_wait(unsigned mbar, unsigned parity) {
    unsigned done;
    do {
        asm volatile("{\n\t.reg .pred p;\n\t"
                     "mbarrier.try_wait.parity.acquire.cta.shared::cta.b64 p, [%1], %2;\n\t"
                     "selp.b32 %0, 1, 0, p;\n\t}"
                     : "=r"(done) : "r"(mbar), "r"(parity) : "memory");
    } while (!done);
}
DEV void mbar_arrive(unsigned mbar) {
    asm volatile("mbarrier.arrive.shared.b64 _, [%0];" :: "r"(mbar) : "memory");
}
DEV void cp_arrive_noinc(unsigned mbar) {
    asm volatile("cp.async.mbarrier.arrive.noinc.shared.b64 [%0];" :: "r"(mbar) : "memory");
}
DEV void ldtm_x32(uint32_t *r, unsigned tmem_addr) {
    asm volatile(
        "tcgen05.ld.sync.aligned.32x32b.x32.b32 "
        "{%0, %1, %2, %3, %4, %5, %6, %7, "
        " %8, %9, %10, %11, %12, %13, %14, %15, "
        " %16, %17, %18, %19, %20, %21, %22, %23, "
        " %24, %25, %26, %27, %28, %29, %30, %31}, [%32];"
        : "=r"(r[0]),  "=r"(r[1]),  "=r"(r[2]),  "=r"(r[3]),
          "=r"(r[4]),  "=r"(r[5]),  "=r"(r[6]),  "=r"(r[7]),
          "=r"(r[8]),  "=r"(r[9]),  "=r"(r[10]), "=r"(r[11]),
          "=r"(r[12]), "=r"(r[13]), "=r"(r[14]), "=r"(r[15]),
          "=r"(r[16]), "=r"(r[17]), "=r"(r[18]), "=r"(r[19]),
          "=r"(r[20]), "=r"(r[21]), "=r"(r[22]), "=r"(r[23]),
          "=r"(r[24]), "=r"(r[25]), "=r"(r[26]), "=r"(r[27]),
          "=r"(r[28]), "=r"(r[29]), "=r"(r[30]), "=r"(r[31])
        : "r"(tmem_addr));
}
#endif  // HAS_TC

// ---------------- weight prep ----------------
__global__ void prep_weights(const float *__restrict__ wq, const float *__restrict__ bq,
                             const float *__restrict__ wk, const float *__restrict__ bk,
                             const float *__restrict__ wv, const float *__restrict__ bv,
                             const float *__restrict__ wo) {
    int idx = blockIdx.x * blockDim.x + threadIdx.x;
    const int W = C * C;
    if (idx < W)            g_wqk[idx] = __float2bfloat16(wq[idx] * 0.0625f);
    else if (idx < 2 * W)   g_wqk[idx] = __float2bfloat16(wk[idx - W]);
    else if (idx < 3 * W)   g_wv[idx - 2 * W] = __float2bfloat16(wv[idx - 2 * W]);
    else if (idx < 4 * W)   g_wo[idx - 3 * W] = __float2bfloat16(wo[idx - 3 * W]);
    else {
        int j = idx - 4 * W;
        if (j < C)           g_bqk[j] = bq[j] * 0.0625f;
        else if (j < 2 * C)  g_bqk[j] = bk[j - C];
        else if (j < 3 * C)  g_bv[j - 2 * C] = bv[j - 2 * C];
    }
}

// ---------------- GroupNorm stats ----------------
__global__ void gn_stats_kernel(const float *__restrict__ x) {
    int bg = blockIdx.x;
    const float4 *p = (const float4 *)(x + (size_t)bg * CPG * NTOK);
    float s = 0.f, sq = 0.f;
    #pragma unroll 4
    for (int i = threadIdx.x; i < CPG * NTOK / 4; i += 256) {
        float4 v = p[i];
        s  += v.x + v.y + v.z + v.w;
        sq += v.x * v.x + v.y * v.y + v.z * v.z + v.w * v.w;
    }
    __shared__ float shm[16];
    int lane = threadIdx.x & 31, wid = threadIdx.x >> 5;
    s = warp_sum(s); sq = warp_sum(sq);
    if (lane == 0) { shm[wid] = s; shm[8 + wid] = sq; }
    __syncthreads();
    if (threadIdx.x == 0) {
        float S = 0.f, Q = 0.f;
        #pragma unroll
        for (int j = 0; j < 8; j++) { S += shm[j]; Q += shm[8 + j]; }
        const float inv = 1.f / (CPG * NTOK);
        float mean = S * inv;
        float var  = Q * inv - mean * mean;
        g_stats[2 * bg]     = mean;
        g_stats[2 * bg + 1] = rsqrtf(var + 1e-5f);
    }
}

// ---------------- GroupNorm apply + transpose -> token-major bf16 ----------------
__global__ void __launch_bounds__(256) gn_apply_t(const float *__restrict__ x,
                                                  const float *__restrict__ gsc,
                                                  const float *__restrict__ gbi) {
    __shared__ float t[32][33];
    int b  = blockIdx.z;
    int n0 = blockIdx.x << 5, c0 = blockIdx.y << 5;
    int tx = threadIdx.x & 31, ty = threadIdx.x >> 5;
    const float *xb = x + (size_t)b * C * NTOK;
    #pragma unroll
    for (int i = 0; i < 4; i++) {
        int c  = c0 + ty + i * 8;
        int bg = b * GRP + (c >> 3);
        float mean = g_stats[2 * bg], rstd = g_stats[2 * bg + 1];
        float a  = rstd * gsc[c];
        float bb = gbi[c] - mean * a;
        t[ty + i * 8][tx] = xb[(size_t)c * NTOK + n0 + tx] * a + bb;
    }
    __syncthreads();
    bf16 *ob = g_xn + (size_t)b * NTOK * C;
    #pragma unroll
    for (int i = 0; i < 4; i++) {
        int n = n0 + ty + i * 8;
        ob[(size_t)n * C + c0 + tx] = __float2bfloat16(t[tx][ty + i * 8]);
    }
}

// ============================================================================
// Warp-specialized persistent GEMM (projections): same as round 13.
// EPI 0: bf16 out + bias[col]   EPI 1: bf16 out + bias[row]
// EPI 2: fp32 out + bias[row] + residual
// ============================================================================
static constexpr int STAGE_BYTES = 3 * 16384;
static constexpr int GEMM_SMEM   = 1024 + 4 * STAGE_BYTES;    // 197632
static constexpr unsigned IDESC_128x128 =
    (1u << 4) | (1u << 7) | (1u << 10) | ((128u / 8) << 17) | ((128u / 16) << 24);

template <int EPI>
__global__ void __launch_bounds__(256)
tc_gemm(const bf16 *__restrict__ A, const bf16 *__restrict__ B,
        int lda, int ldb, int K,
        long long sA, long long sB,
        const float *__restrict__ bias,
        bf16 *__restrict__ outH, float *__restrict__ outF,
        int ldc, long long sC,
        const float *__restrict__ resid,
        int tilesX, int tilesY, int nTiles) {
    extern __shared__ __align__(1024) char smem[];
    const int tid = threadIdx.x, wid = tid >> 5, lane = tid & 31;
    const int G = gridDim.x;

#if HAS_TC
    const unsigned sb = smem_u32(smem);
    const int nch = K / 64;
    const int t0 = blockIdx.x;
    const int nTloc = (nTiles - 1 - t0) / G + 1;
    const int Q = nTloc * nch;

    #define FULLB(s) (sb + 8  + 8 * (s))
    #define FREEB(s) (sb + 40 + 8 * (s))
    #define EPIFB(b) (sb + 72 + 8 * (b))
    #define EPIEB(b) (sb + 88 + 8 * (b))

    auto tile_coords = [&](int ti, int &m0, int &n0, int &bz,
                           const bf16 *&Ab, const bf16 *&Bb) {
        int t = t0 + ti * G;
        int bx = t % tilesX, rem = t / tilesX;
        int by = rem % tilesY; bz = rem / tilesY;
        m0 = by * 128; n0 = bx * 256;
        Ab = A + (size_t)bz * sA; Bb = B + (size_t)bz * sB;
    };

    if (tid == 0) {
        #pragma unroll
        for (int s = 0; s < 4; s++) { mbar_init(FULLB(s), 96); mbar_init(FREEB(s), 1); }
        mbar_init(EPIFB(0), 1); mbar_init(EPIFB(1), 1);
        mbar_init(EPIEB(0), 128); mbar_init(EPIEB(1), 128);
    }
    if (wid == 0) tc_alloc(sb, 512);
    __syncthreads();
    const unsigned tmem = *(volatile unsigned *)smem;

    if (wid >= 5) {
        const int ptid = tid - 160;
        unsigned phF[4] = {1, 1, 1, 1};
        for (int q = 0; q < Q; q++) {
            const int s = q & 3;
            mbar_wait(FREEB(s), phF[s]); phF[s] ^= 1;
            int m0, n0, bz; const bf16 *Ab, *Bb;
            tile_coords(q / nch, m0, n0, bz, Ab, Bb);
            const int kk = (q % nch) * 64;
            const unsigned stb = sb + 1024 + s * STAGE_BYTES;
            const bf16 *b0 = Ab + (size_t)m0 * lda + kk;
            const bf16 *b1 = Bb + (size_t)n0 * ldb + kk;
            const bf16 *b2 = Bb + (size_t)(n0 + 128) * ldb + kk;
            #pragma unroll
            for (int i = 0; i < 32; i++) {
                int g   = i * 96 + ptid;
                int sub = g >> 10, u = g & 1023;
                int r = u >> 3, cc = u & 7;
                const bf16 *srcb = (sub == 0) ? b0 : ((sub == 1) ? b1 : b2);
                int ldx = (sub == 0) ? lda : ldb;
                cp16(stb + sub * 16384 + SW128_SWZ((unsigned)(r * 128 + cc * 16)),
                     srcb + (size_t)r * ldx + cc * 8);
            }
            cp_arrive_noinc(FULLB(s));
        }
    } else if (wid == 4) {
        unsigned phFull[4] = {0, 0, 0, 0};
        unsigned phEF[2]   = {0, 0};
        for (int q = 0; q < Q; q++) {
            const int s = q & 3, c = q % nch, ti = q / nch;
            mbar_wait(FULLB(s), phFull[s]); phFull[s] ^= 1;
            if (c == 0 && ti >= 2) {
                const int b = ti & 1;
                mbar_wait(EPIEB(b), phEF[b]); phEF[b] ^= 1;
            }
            if (lane == 0) {
                fence_proxy_async_cta();
                tc_fence_after();
                const unsigned dbuf = tmem + ((ti & 1) ? 256u : 0u);
                const unsigned stb = sb + 1024 + s * STAGE_BYTES;
                uint64_t ad  = mkdesc(stb);
                uint64_t bd0 = mkdesc(stb + 16384);
                uint64_t bd1 = mkdesc(stb + 32768);
                unsigned en0 = (c > 0);
                #pragma unroll
                for (int k = 0; k < 4; k++) {
                    tc_mma_f16_ss(dbuf,       ad + 2 * k, bd0 + 2 * k, IDESC_128x128, en0 | (k > 0));
                    tc_mma_f16_ss(dbuf + 128, ad + 2 * k, bd1 + 2 * k, IDESC_128x128, en0 | (k > 0));
                }
                tc_commit(FREEB(s));
                if (c == nch - 1) tc_commit(EPIFB(ti & 1));
            }
        }
    } else {
        unsigned phEP[2] = {0, 0};
        for (int ti = 0; ti < nTloc; ti++) {
            const int b = ti & 1;
            mbar_wait(EPIFB(b), phEP[b]); phEP[b] ^= 1;
            tc_fence_after();
            int m0, n0, bz; const bf16 *Ab, *Bb;
            tile_coords(ti, m0, n0, bz, Ab, Bb);
            const unsigned pbuf = tmem + (b ? 256u : 0u);
            const int gr = m0 + wid * 32 + lane;
            const size_t coff = (size_t)bz * sC;
            float rowbias  = (EPI == 1 || EPI == 2) ? bias[gr] : 0.f;
            #pragma unroll
            for (int g = 0; g < 8; g++) {
                uint32_t r[32];
                ldtm_x32(r, pbuf + g * 32);
                tc_wait_ld();
                const int nc0 = n0 + g * 32;
                if (EPI == 2) {
                    const float *rp = resid + coff + (size_t)gr * ldc + nc0;
                    float *op = outF + coff + (size_t)gr * ldc + nc0;
                    #pragma unroll
                    for (int qq = 0; qq < 8; qq++) {
                        float4 rr = ((const float4 *)rp)[qq];
                        ((float4 *)op)[qq] = make_float4(
                            __uint_as_float(r[4 * qq + 0]) + rowbias + rr.x,
                            __uint_as_float(r[4 * qq + 1]) + rowbias + rr.y,
                            __uint_as_float(r[4 * qq + 2]) + rowbias + rr.z,
                            __uint_as_float(r[4 * qq + 3]) + rowbias + rr.w);
                    }
                } else {
                    unsigned w[16];
                    #pragma unroll
                    for (int j = 0; j < 32; j += 2) {
                        float v0 = __uint_as_float(r[j]);
                        float v1 = __uint_as_float(r[j + 1]);
                        if (EPI == 0) { v0 += bias[nc0 + j]; v1 += bias[nc0 + j + 1]; }
                        if (EPI == 1) { v0 += rowbias; v1 += rowbias; }
                        w[j >> 1] = pack_bf16x2(v0, v1);
                    }
                    uint4 *dst = (uint4 *)(outH + coff + (size_t)gr * ldc + nc0);
                    #pragma unroll
                    for (int qq = 0; qq < 4; qq++)
                        dst[qq] = make_uint4(w[4 * qq], w[4 * qq + 1], w[4 * qq + 2], w[4 * qq + 3]);
                }
            }
            tc_fence_before();
            mbar_arrive(EPIEB(b));
        }
    }

    __syncthreads();
    if (wid == 0) { tc_relinq(); tc_dealloc(tmem, 512); }
    #undef FULLB
    #undef FREEB
    #undef EPIFB
    #undef EPIEB

#else
    // mma.sync fallback (correctness only; base-arch pass)
    constexpr int BK = 32;
    constexpr int LDS = 40;
    constexpr int TEL = 128 * LDS;
    bf16 *shA = (bf16 *)smem;
    bf16 *shB = shA + 3 * TEL;
    const int wm = wid >> 2, wn = wid & 3;

    for (int t = blockIdx.x; t < nTiles; t += G) {
        int bx = t % tilesX, rem = t / tilesX;
        int by = rem % tilesY, bz = rem / tilesY;
        const bf16 *Ab = A + (size_t)bz * sA;
        const bf16 *Bb = B + (size_t)bz * sB;
        const int m0 = by * 128, n0 = bx * 256;
        const size_t coff = (size_t)bz * sC;

        for (int nh = 0; nh < 2; nh++) {
            const int n0h = n0 + nh * 128;
            float acc[4][4][4];
            #pragma unroll
            for (int i = 0; i < 4; i++)
                #pragma unroll
                for (int j = 0; j < 4; j++)
                    #pragma unroll
                    for (int r = 0; r < 4; r++) acc[i][j][r] = 0.f;

            const int nk = K / BK;
            auto stage_load = [&](bf16 *sa, bf16 *sbf, int k0) {
                #pragma unroll
                for (int i = 0; i < 2; i++) {
                    int idx = i * 256 + tid;
                    int r = idx >> 2, s = idx & 3;
                    cp16(smem_u32(sa + r * LDS + s * 8), Ab + (size_t)(m0 + r) * lda + k0 + s * 8);
                    cp16(smem_u32(sbf + r * LDS + s * 8), Bb + (size_t)(n0h + r) * ldb + k0 + s * 8);
                }
            };
            stage_load(shA, shB, 0);  cp_commit();
            stage_load(shA + TEL, shB + TEL, BK);  cp_commit();

            const unsigned baseA = smem_u32(shA);
            const unsigned baseB = smem_u32(shB);
            int cst = 0, ldst = 2;
            for (int kt = 0; kt < nk; ++kt) {
                cp_wait<1>();
                __syncthreads();
                if (kt + 2 < nk) stage_load(shA + ldst * TEL, shB + ldst * TEL, (kt + 2) * BK);
                cp_commit();
                ldst = (ldst + 1 == 3) ? 0 : ldst + 1;
                const unsigned aS = baseA + (unsigned)(cst * TEL) * 2u;
                const unsigned bS = baseB + (unsigned)(cst * TEL) * 2u;
                cst = (cst + 1 == 3) ? 0 : cst + 1;
                #pragma unroll
                for (int kk = 0; kk < BK; kk += 16) {
                    unsigned af[4][4];
                    #pragma unroll
                    for (int mi = 0; mi < 4; mi++) {
                        int rrow = wm * 64 + mi * 16 + (lane & 15);
                        int rcol = kk + ((lane >> 4) << 3);
                        ldsm_x4(af[mi][0], af[mi][1], af[mi][2], af[mi][3],
                                aS + (unsigned)(rrow * LDS + rcol) * 2u);
                    }
                    unsigned bfr[4][2];
                    #pragma unroll
                    for (int njp = 0; njp < 2; njp++) {
                        unsigned r0, r1, r2, r3;
                        int rrow = wn * 32 + njp * 16 + (lane & 7) + ((lane >> 4) << 3);
                        int rcol = kk + (((lane >> 3) & 1) << 3);
                        ldsm_x4(r0, r1, r2, r3, bS + (unsigned)(rrow * LDS + rcol) * 2u);
                        bfr[njp * 2][0] = r0; bfr[njp * 2][1] = r1;
                        bfr[njp * 2 + 1][0] = r2; bfr[njp * 2 + 1][1] = r3;
                    }
                    #pragma unroll
                    for (int mi = 0; mi < 4; mi++)
                        #pragma unroll
                        for (int nj = 0; nj < 4; nj++)
                            mma16816(acc[mi][nj], af[mi], bfr[nj]);
                }
                __syncthreads();
            }

            #pragma unroll
            for (int mi = 0; mi < 4; mi++) {
                int mr0 = m0 + wm * 64 + mi * 16 + (lane >> 2);
                int mr1 = mr0 + 8;
                float rb0 = 0.f, rb1 = 0.f;
                if (EPI == 1 || EPI == 2) { rb0 = bias[mr0]; rb1 = bias[mr1]; }
                #pragma unroll
                for (int nj = 0; nj < 4; nj++) {
                    int nc = n0h + wn * 32 + nj * 8 + ((lane & 3) << 1);
                    float v0 = acc[mi][nj][0], v1 = acc[mi][nj][1];
                    float v2 = acc[mi][nj][2], v3 = acc[mi][nj][3];
                    if (EPI == 0) {
                        float c0 = bias[nc], c1 = bias[nc + 1];
                        *(unsigned *)(outH + coff + (size_t)mr0 * ldc + nc) = pack_bf16x2(v0 + c0, v1 + c1);
                        *(unsigned *)(outH + coff + (size_t)mr1 * ldc + nc) = pack_bf16x2(v2 + c0, v3 + c1);
                    } else if (EPI == 1) {
                        *(unsigned *)(outH + coff + (size_t)mr0 * ldc + nc) = pack_bf16x2(v0 + rb0, v1 + rb0);
                        *(unsigned *)(outH + coff + (size_t)mr1 * ldc + nc) = pack_bf16x2(v2 + rb1, v3 + rb1);
                    } else {
                        const float *rp = resid + coff;
                        float2 q0 = *(const float2 *)(rp + (size_t)mr0 * ldc + nc);
                        float2 q1 = *(const float2 *)(rp + (size_t)mr1 * ldc + nc);
                        *(float2 *)(outF + coff + (size_t)mr0 * ldc + nc) = make_float2(v0 + rb0 + q0.x, v1 + rb0 + q0.y);
                        *(float2 *)(outF + coff + (size_t)mr1 * ldc + nc) = make_float2(v2 + rb1 + q1.x, v3 + rb1 + q1.y);
                    }
                }
            }
            __syncthreads();
        }
    }
#endif
}

// ============================================================================
// FUSED ATTENTION (persistent, warp-specialized, flash-style):
//   Round-14 refinements over round 13:
//   - per-kc (64-col) PCONV/PFREE barrier pairs: PV(kc0) overlaps conv(kc1);
//     conversion of tile mt+1 LDTM/exp overlaps PV(mt) (PFREE gates STS only)
//   - LDTM/exp software pipeline inside conversion (exp(g) under LDTM(g+1))
// ============================================================================
static constexpr int SQ_OFF   = 1024;
static constexpr int RING_OFF = SQ_OFF + 65536;       // 66560
static constexpr int SP_OFF   = RING_OFF + 131072;    // 197632
static constexpr int ATT_SMEM = SP_OFF + 32768;       // 230400

__global__ void __launch_bounds__(256)
attn_fused(const bf16 *__restrict__ qk, const bf16 *__restrict__ v,
           bf16 *__restrict__ attnOut) {
    extern __shared__ __align__(1024) char smem[];
    const int tid = threadIdx.x, wid = tid >> 5, lane = tid & 31;
    const int G = gridDim.x;
    const int t0 = blockIdx.x;
    const long long sQK = (long long)NTOK * 512;
    const long long sCN = (long long)C * NTOK;
    const long long sAT = (long long)NTOK * C;
    const int NW = BATCH * 32;

#if HAS_TC
    const unsigned sb = smem_u32(smem);
    #define QF_B    (sb + 8)
    #define QFREE_B (sb + 16)
    #define FULLB(s) (sb + 24 + 8 * (s))
    #define FREEB(s) (sb + 88 + 8 * (s))
    #define SDONE(b) (sb + 152 + 8 * (b))
    #define PCONVB(k) (sb + 168 + 8 * (k))
    #define PFREEB(k) (sb + 184 + 8 * (k))
    #define AFIN_B  (sb + 200)
    #define EPID_B  (sb + 208)

    if (tid == 0) {
        mbar_init(QF_B, 96); mbar_init(QFREE_B, 1);
        #pragma unroll
        for (int s = 0; s < 8; s++) { mbar_init(FULLB(s), 96); mbar_init(FREEB(s), 1); }
        mbar_init(SDONE(0), 1); mbar_init(SDONE(1), 1);
        mbar_init(PCONVB(0), 128); mbar_init(PCONVB(1), 128);
        mbar_init(PFREEB(0), 1);   mbar_init(PFREEB(1), 1);
        mbar_init(AFIN_B, 1); mbar_init(EPID_B, 128);
    }
    if (wid == 0) tc_alloc(sb, 512);
    __syncthreads();
    const unsigned tmem = *(volatile unsigned *)smem;

    if (wid >= 5) {
        // ------------- producers -------------
        const int ptid = tid - 160;
        unsigned phFree[8] = {1, 1, 1, 1, 1, 1, 1, 1};
        unsigned phQFree = 1;
        for (int w = t0; w < NW; w += G) {
            int b = w >> 5, qt = w & 31;
            const bf16 *Qb = qk + (size_t)b * sQK + (size_t)(qt * 128) * 512;
            const bf16 *Kb = qk + (size_t)b * sQK + 256;
            const bf16 *Vb = v  + (size_t)b * sCN;
            mbar_wait(QFREE_B, phQFree); phQFree ^= 1;
            #pragma unroll 4
            for (int i = 0; i < 43; i++) {
                int g = i * 96 + ptid;
                if (g < 4096) {
                    int sub = g >> 10, u = g & 1023, r = u >> 3, cc = u & 7;
                    cp16(sb + SQ_OFF + sub * 16384 + SW128_SWZ((unsigned)(r * 128 + cc * 16)),
                         Qb + (size_t)r * 512 + sub * 64 + cc * 8);
                }
            }
            cp_arrive_noinc(QF_B);
            for (int mt = 0; mt < 32; mt++) {
                #pragma unroll
                for (int j = 0; j < 4; j++) {          // k chunks, stages 0..3
                    mbar_wait(FREEB(j), phFree[j]); phFree[j] ^= 1;
                    const bf16 *src = Kb + (size_t)(mt * 128) * 512 + j * 64;
                    #pragma unroll
                    for (int i = 0; i < 11; i++) {
                        int g = i * 96 + ptid;
                        if (g < 1024) {
                            int r = g >> 3, cc = g & 7;
                            cp16(sb + RING_OFF + j * 16384 + SW128_SWZ((unsigned)(r * 128 + cc * 16)),
                                 src + (size_t)r * 512 + cc * 8);
                        }
                    }
                    cp_arrive_noinc(FULLB(j));
                }
                #pragma unroll
                for (int vt = 0; vt < 4; vt++) {       // v tiles, stages 4..7 (kc=vt>>1, nh=vt&1)
                    int s = 4 + vt, kc = vt >> 1, nh = vt & 1;
                    mbar_wait(FREEB(s), phFree[s]); phFree[s] ^= 1;
                    const bf16 *src = Vb + (size_t)(nh * 128) * NTOK + mt * 128 + kc * 64;
                    #pragma unroll
                    for (int i = 0; i < 11; i++) {
                        int g = i * 96 + ptid;
                        if (g < 1024) {
                            int r = g >> 3, cc = g & 7;
                            cp16(sb + RING_OFF + s * 16384 + SW128_SWZ((unsigned)(r * 128 + cc * 16)),
                                 src + (size_t)r * NTOK + cc * 8);
                        }
                    }
                    cp_arrive_noinc(FULLB(s));
                }
            }
        }
    } else if (wid == 4) {
        // ------------- MMA issuer -------------
        unsigned phFull[8] = {0, 0, 0, 0, 0, 0, 0, 0};
        unsigned phPC[2] = {0, 0};
        unsigned phED = 1, phQF = 0;
        for (int w = t0; w < NW; w += G) {
            mbar_wait(QF_B, phQF); phQF ^= 1;
            auto issueS = [&](int mt) {
                unsigned sbt = tmem + ((mt & 1) ? 128u : 0u);
                #pragma unroll
                for (int j = 0; j < 4; j++) {
                    mbar_wait(FULLB(j), phFull[j]); phFull[j] ^= 1;
                    if (lane == 0) {
                        fence_proxy_async_cta();
                        tc_fence_after();
                        uint64_t ad = mkdesc(sb + SQ_OFF + j * 16384);
                        uint64_t bd = mkdesc(sb + RING_OFF + j * 16384);
                        #pragma unroll
                        for (int k = 0; k < 4; k++)
                            tc_mma_f16_ss(sbt, ad + 2 * k, bd + 2 * k, IDESC_128x128, (j > 0) | (k > 0));
                        tc_commit(FREEB(j));
                    }
                }
                if (lane == 0) tc_commit(SDONE(mt & 1));
            };
            issueS(0);
            for (int mt = 0; mt < 32; mt++) {
                if (mt + 1 < 32) issueS(mt + 1);
                else if (lane == 0) tc_commit(QFREE_B);
                if (mt == 0) { mbar_wait(EPID_B, phED); phED ^= 1; }
                #pragma unroll
                for (int kc = 0; kc < 2; kc++) {
                    mbar_wait(PCONVB(kc), phPC[kc]); phPC[kc] ^= 1;
                    #pragma unroll
                    for (int nh = 0; nh < 2; nh++) {
                        int s = 4 + kc * 2 + nh;
                        mbar_wait(FULLB(s), phFull[s]); phFull[s] ^= 1;
                        if (lane == 0) {
                            fence_proxy_async_cta();
                            tc_fence_after();
                            uint64_t ad = mkdesc(sb + SP_OFF + kc * 16384);
                            uint64_t bd = mkdesc(sb + RING_OFF + s * 16384);
                            unsigned dD = tmem + 256 + nh * 128;
                            unsigned en0 = (mt > 0) | (kc > 0);
                            #pragma unroll
                            for (int k = 0; k < 4; k++)
                                tc_mma_f16_ss(dD, ad + 2 * k, bd + 2 * k, IDESC_128x128, en0 | (k > 0));
                            tc_commit(FREEB(s));
                        }
                    }
                    if (lane == 0) tc_commit(PFREEB(kc));
                }
                if (mt == 31 && lane == 0) tc_commit(AFIN_B);
            }
        }
    } else {
        // ------------- epilogue (warps 0-3): pipelined S conversion -------------
        unsigned phSD[2] = {0, 0};
        unsigned phPF[2] = {1, 1};
        unsigned phAF = 0;
        const int row = wid * 32 + lane;
        for (int w = t0; w < NW; w += G) {
            int b = w >> 5, qt = w & 31;
            const int gr = qt * 128 + row;
            float rsum = 0.f;
            for (int mt = 0; mt < 32; mt++) {
                const int sbz = mt & 1;
                mbar_wait(SDONE(sbz), phSD[sbz]); phSD[sbz] ^= 1;
                tc_fence_after();
                const unsigned sbuf = tmem + (sbz ? 128u : 0u);
                #pragma unroll
                for (int kc = 0; kc < 2; kc++) {
                    uint32_t r0[32], r1[32];
                    ldtm_x32(r0, sbuf + (2 * kc) * 32);
                    tc_wait_ld();
                    ldtm_x32(r1, sbuf + (2 * kc + 1) * 32);   // async under exp(r0)
                    uint4 pk0[4], pk1[4];
                    #pragma unroll
                    for (int uu = 0; uu < 4; uu++) {
                        float e[8];
                        #pragma unroll
                        for (int j = 0; j < 8; j++) {
                            e[j] = __expf(__uint_as_float(r0[uu * 8 + j]));
                            rsum += e[j];
                        }
                        pk0[uu] = make_uint4(pack_bf16x2(e[0], e[1]), pack_bf16x2(e[2], e[3]),
                                             pack_bf16x2(e[4], e[5]), pack_bf16x2(e[6], e[7]));
                    }
                    tc_wait_ld();
                    #pragma unroll
                    for (int uu = 0; uu < 4; uu++) {
                        float e[8];
                        #pragma unroll
                        for (int j = 0; j < 8; j++) {
                            e[j] = __expf(__uint_as_float(r1[uu * 8 + j]));
                            rsum += e[j];
                        }
                        pk1[uu] = make_uint4(pack_bf16x2(e[0], e[1]), pack_bf16x2(e[2], e[3]),
                                             pack_bf16x2(e[4], e[5]), pack_bf16x2(e[6], e[7]));
                    }
                    mbar_wait(PFREEB(kc), phPF[kc]); phPF[kc] ^= 1;   // PV(mt-1) done with chunk
                    #pragma unroll
                    for (int uu = 0; uu < 4; uu++) {
                        *(uint4 *)(smem + SP_OFF + kc * 16384 +
                                   SW128_SWZ((unsigned)(row * 128 + uu * 16))) = pk0[uu];
                        *(uint4 *)(smem + SP_OFF + kc * 16384 +
                                   SW128_SWZ((unsigned)(row * 128 + (4 + uu) * 16))) = pk1[uu];
                    }
                    fence_proxy_async_cta();
                    mbar_arrive(PCONVB(kc));
                }
            }
            mbar_wait(AFIN_B, phAF); phAF ^= 1;
            tc_fence_after();
            const float scale = __frcp_rn(rsum);
            bf16 *orow = attnOut + (size_t)b * sAT + (size_t)gr * 256;
            #pragma unroll
            for (int g = 0; g < 8; g++) {
                uint32_t r[32];
                ldtm_x32(r, tmem + 256 + g * 32);
                tc_wait_ld();
                unsigned wpk[16];
                #pragma unroll
                for (int j = 0; j < 32; j += 2)
                    wpk[j >> 1] = pack_bf16x2(__uint_as_float(r[j]) * scale,
                                              __uint_as_float(r[j + 1]) * scale);
                uint4 *dst = (uint4 *)(orow + g * 32);
                #pragma unroll
                for (int qq = 0; qq < 4; qq++)
                    dst[qq] = make_uint4(wpk[4 * qq], wpk[4 * qq + 1], wpk[4 * qq + 2], wpk[4 * qq + 3]);
            }
            tc_fence_before();
            mbar_arrive(EPID_B);
        }
    }

    __syncthreads();
    if (wid == 0) { tc_relinq(); tc_dealloc(tmem, 512); }
    #undef QF_B
    #undef QFREE_B
    #undef FULLB
    #undef FREEB
    #undef SDONE
    #undef PCONVB
    #undef PFREEB
    #undef AFIN_B
    #undef EPID_B

#else
    // ---- slow-but-correct fallback (base-arch pass; never the loaded cubin) ----
    for (int w = t0; w < NW; w += G) {
        int b = w >> 5, qt = w & 31;
        const bf16 *Qb = qk + (size_t)b * sQK;
        const bf16 *Kb = qk + (size_t)b * sQK + 256;
        const bf16 *Vb = v  + (size_t)b * sCN;
        for (int rr = wid; rr < 128; rr += 8) {
            int n = qt * 128 + rr;
            float qreg[8];
            #pragma unroll
            for (int i = 0; i < 8; i++)
                qreg[i] = __bfloat162float(Qb[(size_t)n * 512 + lane * 8 + i]);
            float acc[8];
            #pragma unroll
            for (int i = 0; i < 8; i++) acc[i] = 0.f;
            float rsum = 0.f;
            for (int m = 0; m < NTOK; m++) {
                float s = 0.f;
                #pragma unroll
                for (int i = 0; i < 8; i++)
                    s += qreg[i] * __bfloat162float(Kb[(size_t)m * 512 + lane * 8 + i]);
                s = warp_sum(s);
                float p = __bfloat162float(__float2bfloat16(__expf(s)));
                if (lane == 0) rsum += p;
                #pragma unroll
                for (int i = 0; i < 8; i++)
                    acc[i] += p * __bfloat162float(Vb[(size_t)(lane * 8 + i) * NTOK + m]);
            }
            rsum = __shfl_sync(0xffffffffu, rsum, 0);
            float inv = 1.f / rsum;
            #pragma unroll
            for (int i = 0; i < 8; i++)
                attnOut[(size_t)b * sAT + (size_t)n * 256 + lane * 8 + i] =
                    __float2bfloat16(acc[i] * inv);
        }
    }
#endif
}

// ---------------- launch ----------------
extern "C" void kernel_launch(void *const *d_in, const int *in_sizes, int n_in,
                              void *d_out, int out_size) {
    const float *x   = (const float *)d_in[0];
    const float *gsc = (const float *)d_in[1];
    const float *gbi = (const float *)d_in[2];
    const float *wq  = (const float *)d_in[3];
    const float *bq  = (const float *)d_in[4];
    const float *wk  = (const float *)d_in[5];
    const float *bk  = (const float *)d_in[6];
    const float *wv  = (const float *)d_in[7];
    const float *bv  = (const float *)d_in[8];
    const float *wo  = (const float *)d_in[9];
    const float *bo  = (const float *)d_in[10];
    float *out = (float *)d_out;

    void *p_xn, *p_wqk, *p_wv, *p_wo, *p_bqk, *p_bv, *p_qk, *p_v, *p_attn;
    cudaGetSymbolAddress(&p_xn, g_xn);
    cudaGetSymbolAddress(&p_wqk, g_wqk);
    cudaGetSymbolAddress(&p_wv, g_wv);
    cudaGetSymbolAddress(&p_wo, g_wo);
    cudaGetSymbolAddress(&p_bqk, g_bqk);
    cudaGetSymbolAddress(&p_bv, g_bv);
    cudaGetSymbolAddress(&p_qk, g_qk);
    cudaGetSymbolAddress(&p_v, g_v);
    cudaGetSymbolAddress(&p_attn, g_attn);

    const long long sCN = (long long)C * NTOK;
    const long long sQK = (long long)NTOK * 512;
    const long long sAT = (long long)NTOK * C;

    cudaFuncSetAttribute(tc_gemm<0>, cudaFuncAttributeMaxDynamicSharedMemorySize, GEMM_SMEM);
    cudaFuncSetAttribute(tc_gemm<1>, cudaFuncAttributeMaxDynamicSharedMemorySize, GEMM_SMEM);
    cudaFuncSetAttribute(tc_gemm<2>, cudaFuncAttributeMaxDynamicSharedMemorySize, GEMM_SMEM);
    cudaFuncSetAttribute(attn_fused, cudaFuncAttributeMaxDynamicSharedMemorySize, ATT_SMEM);

    auto gsz = [](int T) { return T < 148 ? T : 148; };

    prep_weights<<<(4 * C * C + 3 * C + 255) / 256, 256>>>(wq, bq, wk, bk, wv, bv, wo);
    gn_stats_kernel<<<BATCH * GRP, 256>>>(x);
    gn_apply_t<<<dim3(NTOK / 32, C / 32, BATCH), 256>>>(x, gsc, gbi);

    // 1) qk_t[n, o] = xn_t[n,:] . wqk[o,:]  + bias[col o]
    tc_gemm<0><<<gsz(512), 256, GEMM_SMEM>>>(
        (const bf16 *)p_xn, (const bf16 *)p_wqk, C, C, C,
        sCN, 0LL, (const float *)p_bqk,
        (bf16 *)p_qk, nullptr, 512, sQK, nullptr, 2, 32, 512);

    // 2) v[o, m] = wv[o,:] . xn_t[m,:]  + bias[row o]
    tc_gemm<1><<<gsz(256), 256, GEMM_SMEM>>>(
        (const bf16 *)p_wv, (const bf16 *)p_xn, C, C, C,
        0LL, sCN, (const float *)p_bv,
        (bf16 *)p_v, nullptr, NTOK, sCN, nullptr, 16, 2, 256);

    // 3+4) fused attention -> g_attn (token-major [n][c], already /rowsum)
    attn_fused<<<gsz(256), 256, ATT_SMEM>>>(
        (const bf16 *)p_qk, (const bf16 *)p_v, (bf16 *)p_attn);

    // 5) out[o, n] = x[o, n] + wo[o,:] . attn_t[n,:] + bo[o]
    tc_gemm<2><<<gsz(256), 256, GEMM_SMEM>>>(
        (const bf16 *)p_wo, (const bf16 *)p_attn, C, C, C,
        0LL, sAT, bo,
        nullptr, out, NTOK, sCN, x, 16, 2, 256);
}

// round 16
// speedup vs baseline: 1.0926x; 1.0926x over previous
#include <cuda_runtime.h>
#include <cuda_bf16.h>
#include <cstdint>

using bf16  = __nv_bfloat16;

#define DEV __device__ __forceinline__

#if defined(__CUDA_ARCH_FEAT_SM103_ALL) || defined(__CUDA_ARCH_FEAT_SM100_ALL) || defined(__CUDA_ARCH_FEAT_SM101_ALL)
#define HAS_TC 1
#else
#define HAS_TC 0
#endif

static constexpr int BATCH = 8;
static constexpr int C     = 256;
static constexpr int NTOK  = 4096;
static constexpr int GRP   = 32;
static constexpr int CPG   = C / GRP;

// ---------------- static device scratch ----------------
__device__ float g_stats[BATCH * GRP * 2];
__device__ bf16  g_xn  [(size_t)BATCH * NTOK * C];
__device__ bf16  g_wqk [512 * 256];
__device__ bf16  g_wv  [256 * 256];
__device__ bf16  g_wo  [256 * 256];
__device__ float g_bqk [512];
__device__ float g_bv  [256];
__device__ bf16  g_qk  [(size_t)BATCH * NTOK * 512];
__device__ bf16  g_v   [(size_t)BATCH * 256 * NTOK];
__device__ bf16  g_attn[(size_t)BATCH * NTOK * 256];

// ---------------- helpers ----------------
DEV float warp_sum(float v) {
    #pragma unroll
    for (int o = 16; o; o >>= 1) v += __shfl_xor_sync(0xffffffffu, v, o);
    return v;
}
DEV unsigned smem_u32(const void *p) { return (unsigned)__cvta_generic_to_shared(p); }

DEV void cp16(unsigned dst_smem, const bf16 *src) {
    asm volatile("cp.async.cg.shared.global [%0], [%1], 16;\n" :: "r"(dst_smem), "l"(src));
}
DEV void cp_commit() { asm volatile("cp.async.commit_group;\n"); }
template <int N> DEV void cp_wait() { asm volatile("cp.async.wait_group %0;\n" :: "n"(N)); }

DEV unsigned pack_bf16x2(float lo, float hi) {
    unsigned r;
    asm("cvt.rn.bf16x2.f32 %0, %1, %2;" : "=r"(r) : "f"(hi), "f"(lo));
    return r;
}

// ---- mma.sync fallback primitives ----
DEV void ldsm_x4(unsigned &r0, unsigned &r1, unsigned &r2, unsigned &r3, unsigned addr) {
    asm volatile("ldmatrix.sync.aligned.m8n8.x4.shared.b16 {%0,%1,%2,%3}, [%4];"
                 : "=r"(r0), "=r"(r1), "=r"(r2), "=r"(r3) : "r"(addr));
}
DEV void mma16816(float *d, const unsigned *a, const unsigned *b) {
    asm volatile("mma.sync.aligned.m16n8k16.row.col.f32.bf16.bf16.f32 "
                 "{%0,%1,%2,%3}, {%4,%5,%6,%7}, {%8,%9}, {%0,%1,%2,%3};"
                 : "+f"(d[0]), "+f"(d[1]), "+f"(d[2]), "+f"(d[3])
                 : "r"(a[0]), "r"(a[1]), "r"(a[2]), "r"(a[3]), "r"(b[0]), "r"(b[1]));
}

// ---- tcgen05 primitives ----
#define SW128_SWZ(off) ((off) ^ (((off) >> 3) & 0x70))
static constexpr uint64_t DESC_BASE =
    (uint64_t(2) << 61) | (uint64_t(1) << 46) | (uint64_t(64) << 32) | (uint64_t(1) << 16);
DEV uint64_t mkdesc(unsigned smem_addr) { return DESC_BASE | ((smem_addr >> 4) & 0x3FFF); }

#if HAS_TC
DEV void tc_alloc(unsigned smem_dst, unsigned ncols) {
    asm volatile("tcgen05.alloc.cta_group::1.sync.aligned.shared::cta.b32 [%0], %1;"
                 :: "r"(smem_dst), "r"(ncols) : "memory");
}
DEV void tc_dealloc(unsigned tmem, unsigned ncols) {
    asm volatile("tcgen05.dealloc.cta_group::1.sync.aligned.b32 %0, %1;" :: "r"(tmem), "r"(ncols));
}
DEV void tc_relinq() {
    asm volatile("tcgen05.relinquish_alloc_permit.cta_group::1.sync.aligned;");
}
DEV void tc_mma_f16_ss(unsigned d, uint64_t ad, uint64_t bd, unsigned idesc, unsigned en) {
    asm volatile("{\n\t.reg .pred p;\n\tsetp.ne.u32 p, %5, 0;\n\t"
                 "tcgen05.mma.cta_group::1.kind::f16 [%0], %1, %2, %3, {%4, %4, %4, %4}, p;\n\t}"
                 :: "r"(d), "l"(ad), "l"(bd), "r"(idesc), "r"(0u), "r"(en) : "memory");
}
DEV void tc_commit(unsigned mbar) {
    asm volatile("tcgen05.commit.cta_group::1.mbarrier::arrive::one.shared::cluster.b64 [%0];"
                 :: "r"(mbar) : "memory");
}
DEV void tc_fence_after() { asm volatile("tcgen05.fence::after_thread_sync;" ::: "memory"); }
DEV void tc_fence_before() { asm volatile("tcgen05.fence::before_thread_sync;" ::: "memory"); }
DEV void tc_wait_ld() { asm volatile("tcgen05.wait::ld.sync.aligned;" ::: "memory"); }
DEV void fence_proxy_async_cta() { asm volatile("fence.proxy.async.shared::cta;" ::: "memory"); }
DEV void mbar_init(unsigned mbar, unsigned cnt) {
    asm volatile("mbarrier.init.shared.b64 [%0], %1;" :: "r"(mbar), "r"(cnt) : "memory");
}
DEV void mbar_wait(unsigned mbar, unsigned parity) {
    unsigned done;
    do {
        asm volatile("{\n\t.reg .pred p;\n\t"
                     "mbarrier.try_wait.parity.acquire.cta.shared::cta.b64 p, [%1], %2;\n\t"
                     "selp.b32 %0, 1, 0, p;\n\t}"
                     : "=r"(done) : "r"(mbar), "r"(parity) : "memory");
    } while (!done);
}
DEV void mbar_arrive(unsigned mbar) {
    asm volatile("mbarrier.arrive.shared.b64 _, [%0];" :: "r"(mbar) : "memory");
}
DEV void cp_arrive_noinc(unsigned mbar) {
    asm volatile("cp.async.mbarrier.arrive.noinc.shared.b64 [%0];" :: "r"(mbar) : "memory");
}
DEV void ldtm_x32(uint32_t *r, unsigned tmem_addr) {
    asm volatile(
        "tcgen05.ld.sync.aligned.32x32b.x32.b32 "
        "{%0, %1, %2, %3, %4, %5, %6, %7, "
        " %8, %9, %10, %11, %12, %13, %14, %15, "
        " %16, %17, %18, %19, %20, %21, %22, %23, "
        " %24, %25, %26, %27, %28, %29, %30, %31}, [%32];"
        : "=r"(r[0]),  "=r"(r[1]),  "=r"(r[2]),  "=r"(r[3]),
          "=r"(r[4]),  "=r"(r[5]),  "=r"(r[6]),  "=r"(r[7]),
          "=r"(r[8]),  "=r"(r[9]),  "=r"(r[10]), "=r"(r[11]),
          "=r"(r[12]), "=r"(r[13]), "=r"(r[14]), "=r"(r[15]),
          "=r"(r[16]), "=r"(r[17]), "=r"(r[18]), "=r"(r[19]),
          "=r"(r[20]), "=r"(r[21]), "=r"(r[22]), "=r"(r[23]),
          "=r"(r[24]), "=r"(r[25]), "=r"(r[26]), "=r"(r[27]),
          "=r"(r[28]), "=r"(r[29]), "=r"(r[30]), "=r"(r[31])
        : "r"(tmem_addr));
}
#endif  // HAS_TC

// ---------------- weight prep ----------------
__global__ void prep_weights(const float *__restrict__ wq, const float *__restrict__ bq,
                             const float *__restrict__ wk, const float *__restrict__ bk,
                             const float *__restrict__ wv, const float *__restrict__ bv,
                             const float *__restrict__ wo) {
    int idx = blockIdx.x * blockDim.x + threadIdx.x;
    const int W = C * C;
    if (idx < W)            g_wqk[idx] = __float2bfloat16(wq[idx] * 0.0625f);
    else if (idx < 2 * W)   g_wqk[idx] = __float2bfloat16(wk[idx - W]);
    else if (idx < 3 * W)   g_wv[idx - 2 * W] = __float2bfloat16(wv[idx - 2 * W]);
    else if (idx < 4 * W)   g_wo[idx - 3 * W] = __float2bfloat16(wo[idx - 3 * W]);
    else {
        int j = idx - 4 * W;
        if (j < C)           g_bqk[j] = bq[j] * 0.0625f;
        else if (j < 2 * C)  g_bqk[j] = bk[j - C];
        else if (j < 3 * C)  g_bv[j - 2 * C] = bv[j - 2 * C];
    }
}

// ---------------- GroupNorm stats ----------------
__global__ void gn_stats_kernel(const float *__restrict__ x) {
    int bg = blockIdx.x;
    const float4 *p = (const float4 *)(x + (size_t)bg * CPG * NTOK);
    float s = 0.f, sq = 0.f;
    #pragma unroll 4
    for (int i = threadIdx.x; i < CPG * NTOK / 4; i += 256) {
        float4 v = p[i];
        s  += v.x + v.y + v.z + v.w;
        sq += v.x * v.x + v.y * v.y + v.z * v.z + v.w * v.w;
    }
    __shared__ float shm[16];
    int lane = threadIdx.x & 31, wid = threadIdx.x >> 5;
    s = warp_sum(s); sq = warp_sum(sq);
    if (lane == 0) { shm[wid] = s; shm[8 + wid] = sq; }
    __syncthreads();
    if (threadIdx.x == 0) {
        float S = 0.f, Q = 0.f;
        #pragma unroll
        for (int j = 0; j < 8; j++) { S += shm[j]; Q += shm[8 + j]; }
        const float inv = 1.f / (CPG * NTOK);
        float mean = S * inv;
        float var  = Q * inv - mean * mean;
        g_stats[2 * bg]     = mean;
        g_stats[2 * bg + 1] = rsqrtf(var + 1e-5f);
    }
}

// ---------------- GroupNorm apply + transpose -> token-major bf16 ----------------
__global__ void __launch_bounds__(256) gn_apply_t(const float *__restrict__ x,
                                                  const float *__restrict__ gsc,
                                                  const float *__restrict__ gbi) {
    __shared__ float t[32][33];
    int b  = blockIdx.z;
    int n0 = blockIdx.x << 5, c0 = blockIdx.y << 5;
    int tx = threadIdx.x & 31, ty = threadIdx.x >> 5;
    const float *xb = x + (size_t)b * C * NTOK;
    #pragma unroll
    for (int i = 0; i < 4; i++) {
        int c  = c0 + ty + i * 8;
        int bg = b * GRP + (c >> 3);
        float mean = g_stats[2 * bg], rstd = g_stats[2 * bg + 1];
        float a  = rstd * gsc[c];
        float bb = gbi[c] - mean * a;
        t[ty + i * 8][tx] = xb[(size_t)c * NTOK + n0 + tx] * a + bb;
    }
    __syncthreads();
    bf16 *ob = g_xn + (size_t)b * NTOK * C;
    #pragma unroll
    for (int i = 0; i < 4; i++) {
        int n = n0 + ty + i * 8;
        ob[(size_t)n * C + c0 + tx] = __float2bfloat16(t[tx][ty + i * 8]);
    }
}

// ============================================================================
// Warp-specialized persistent GEMM (projections): unchanged from round 13.
// ============================================================================
static constexpr int STAGE_BYTES = 3 * 16384;
static constexpr int GEMM_SMEM   = 1024 + 4 * STAGE_BYTES;    // 197632
static constexpr unsigned IDESC_128x128 =
    (1u << 4) | (1u << 7) | (1u << 10) | ((128u / 8) << 17) | ((128u / 16) << 24);

template <int EPI>
__global__ void __launch_bounds__(256)
tc_gemm(const bf16 *__restrict__ A, const bf16 *__restrict__ B,
        int lda, int ldb, int K,
        long long sA, long long sB,
        const float *__restrict__ bias,
        bf16 *__restrict__ outH, float *__restrict__ outF,
        int ldc, long long sC,
        const float *__restrict__ resid,
        int tilesX, int tilesY, int nTiles) {
    extern __shared__ __align__(1024) char smem[];
    const int tid = threadIdx.x, wid = tid >> 5, lane = tid & 31;
    const int G = gridDim.x;

#if HAS_TC
    const unsigned sb = smem_u32(smem);
    const int nch = K / 64;
    const int t0 = blockIdx.x;
    const int nTloc = (nTiles - 1 - t0) / G + 1;
    const int Q = nTloc * nch;

    #define FULLB(s) (sb + 8  + 8 * (s))
    #define FREEB(s) (sb + 40 + 8 * (s))
    #define EPIFB(b) (sb + 72 + 8 * (b))
    #define EPIEB(b) (sb + 88 + 8 * (b))

    auto tile_coords = [&](int ti, int &m0, int &n0, int &bz,
                           const bf16 *&Ab, const bf16 *&Bb) {
        int t = t0 + ti * G;
        int bx = t % tilesX, rem = t / tilesX;
        int by = rem % tilesY; bz = rem / tilesY;
        m0 = by * 128; n0 = bx * 256;
        Ab = A + (size_t)bz * sA; Bb = B + (size_t)bz * sB;
    };

    if (tid == 0) {
        #pragma unroll
        for (int s = 0; s < 4; s++) { mbar_init(FULLB(s), 96); mbar_init(FREEB(s), 1); }
        mbar_init(EPIFB(0), 1); mbar_init(EPIFB(1), 1);
        mbar_init(EPIEB(0), 128); mbar_init(EPIEB(1), 128);
    }
    if (wid == 0) tc_alloc(sb, 512);
    __syncthreads();
    const unsigned tmem = *(volatile unsigned *)smem;

    if (wid >= 5) {
        const int ptid = tid - 160;
        unsigned phF[4] = {1, 1, 1, 1};
        for (int q = 0; q < Q; q++) {
            const int s = q & 3;
            mbar_wait(FREEB(s), phF[s]); phF[s] ^= 1;
            int m0, n0, bz; const bf16 *Ab, *Bb;
            tile_coords(q / nch, m0, n0, bz, Ab, Bb);
            const int kk = (q % nch) * 64;
            const unsigned stb = sb + 1024 + s * STAGE_BYTES;
            const bf16 *b0 = Ab + (size_t)m0 * lda + kk;
            const bf16 *b1 = Bb + (size_t)n0 * ldb + kk;
            const bf16 *b2 = Bb + (size_t)(n0 + 128) * ldb + kk;
            #pragma unroll
            for (int i = 0; i < 32; i++) {
                int g   = i * 96 + ptid;
                int sub = g >> 10, u = g & 1023;
                int r = u >> 3, cc = u & 7;
                const bf16 *srcb = (sub == 0) ? b0 : ((sub == 1) ? b1 : b2);
                int ldx = (sub == 0) ? lda : ldb;
                cp16(stb + sub * 16384 + SW128_SWZ((unsigned)(r * 128 + cc * 16)),
                     srcb + (size_t)r * ldx + cc * 8);
            }
            cp_arrive_noinc(FULLB(s));
        }
    } else if (wid == 4) {
        unsigned phFull[4] = {0, 0, 0, 0};
        unsigned phEF[2]   = {0, 0};
        for (int q = 0; q < Q; q++) {
            const int s = q & 3, c = q % nch, ti = q / nch;
            mbar_wait(FULLB(s), phFull[s]); phFull[s] ^= 1;
            if (c == 0 && ti >= 2) {
                const int b = ti & 1;
                mbar_wait(EPIEB(b), phEF[b]); phEF[b] ^= 1;
            }
            if (lane == 0) {
                fence_proxy_async_cta();
                tc_fence_after();
                const unsigned dbuf = tmem + ((ti & 1) ? 256u : 0u);
                const unsigned stb = sb + 1024 + s * STAGE_BYTES;
                uint64_t ad  = mkdesc(stb);
                uint64_t bd0 = mkdesc(stb + 16384);
                uint64_t bd1 = mkdesc(stb + 32768);
                unsigned en0 = (c > 0);
                #pragma unroll
                for (int k = 0; k < 4; k++) {
                    tc_mma_f16_ss(dbuf,       ad + 2 * k, bd0 + 2 * k, IDESC_128x128, en0 | (k > 0));
                    tc_mma_f16_ss(dbuf + 128, ad + 2 * k, bd1 + 2 * k, IDESC_128x128, en0 | (k > 0));
                }
                tc_commit(FREEB(s));
                if (c == nch - 1) tc_commit(EPIFB(ti & 1));
            }
        }
    } else {
        unsigned phEP[2] = {0, 0};
        for (int ti = 0; ti < nTloc; ti++) {
            const int b = ti & 1;
            mbar_wait(EPIFB(b), phEP[b]); phEP[b] ^= 1;
            tc_fence_after();
            int m0, n0, bz; const bf16 *Ab, *Bb;
            tile_coords(ti, m0, n0, bz, Ab, Bb);
            const unsigned pbuf = tmem + (b ? 256u : 0u);
            const int gr = m0 + wid * 32 + lane;
            const size_t coff = (size_t)bz * sC;
            float rowbias  = (EPI == 1 || EPI == 2) ? bias[gr] : 0.f;
            #pragma unroll
            for (int g = 0; g < 8; g++) {
                uint32_t r[32];
                ldtm_x32(r, pbuf + g * 32);
                tc_wait_ld();
                const int nc0 = n0 + g * 32;
                if (EPI == 2) {
                    const float *rp = resid + coff + (size_t)gr * ldc + nc0;
                    float *op = outF + coff + (size_t)gr * ldc + nc0;
                    #pragma unroll
                    for (int qq = 0; qq < 8; qq++) {
                        float4 rr = ((const float4 *)rp)[qq];
                        ((float4 *)op)[qq] = make_float4(
                            __uint_as_float(r[4 * qq + 0]) + rowbias + rr.x,
                            __uint_as_float(r[4 * qq + 1]) + rowbias + rr.y,
                            __uint_as_float(r[4 * qq + 2]) + rowbias + rr.z,
                            __uint_as_float(r[4 * qq + 3]) + rowbias + rr.w);
                    }
                } else {
                    unsigned w[16];
                    #pragma unroll
                    for (int j = 0; j < 32; j += 2) {
                        float v0 = __uint_as_float(r[j]);
                        float v1 = __uint_as_float(r[j + 1]);
                        if (EPI == 0) { v0 += bias[nc0 + j]; v1 += bias[nc0 + j + 1]; }
                        if (EPI == 1) { v0 += rowbias; v1 += rowbias; }
                        w[j >> 1] = pack_bf16x2(v0, v1);
                    }
                    uint4 *dst = (uint4 *)(outH + coff + (size_t)gr * ldc + nc0);
                    #pragma unroll
                    for (int qq = 0; qq < 4; qq++)
                        dst[qq] = make_uint4(w[4 * qq], w[4 * qq + 1], w[4 * qq + 2], w[4 * qq + 3]);
                }
            }
            tc_fence_before();
            mbar_arrive(EPIEB(b));
        }
    }

    __syncthreads();
    if (wid == 0) { tc_relinq(); tc_dealloc(tmem, 512); }
    #undef FULLB
    #undef FREEB
    #undef EPIFB
    #undef EPIEB

#else
    // mma.sync fallback (correctness only; base-arch pass)
    constexpr int BK = 32;
    constexpr int LDS = 40;
    constexpr int TEL = 128 * LDS;
    bf16 *shA = (bf16 *)smem;
    bf16 *shB = shA + 3 * TEL;
    const int wm = wid >> 2, wn = wid & 3;

    for (int t = blockIdx.x; t < nTiles; t += G) {
        int bx = t % tilesX, rem = t / tilesX;
        int by = rem % tilesY, bz = rem / tilesY;
        const bf16 *Ab = A + (size_t)bz * sA;
        const bf16 *Bb = B + (size_t)bz * sB;
        const int m0 = by * 128, n0 = bx * 256;
        const size_t coff = (size_t)bz * sC;

        for (int nh = 0; nh < 2; nh++) {
            const int n0h = n0 + nh * 128;
            float acc[4][4][4];
            #pragma unroll
            for (int i = 0; i < 4; i++)
                #pragma unroll
                for (int j = 0; j < 4; j++)
                    #pragma unroll
                    for (int r = 0; r < 4; r++) acc[i][j][r] = 0.f;

            const int nk = K / BK;
            auto stage_load = [&](bf16 *sa, bf16 *sbf, int k0) {
                #pragma unroll
                for (int i = 0; i < 2; i++) {
                    int idx = i * 256 + tid;
                    int r = idx >> 2, s = idx & 3;
                    cp16(smem_u32(sa + r * LDS + s * 8), Ab + (size_t)(m0 + r) * lda + k0 + s * 8);
                    cp16(smem_u32(sbf + r * LDS + s * 8), Bb + (size_t)(n0h + r) * ldb + k0 + s * 8);
                }
            };
            stage_load(shA, shB, 0);  cp_commit();
            stage_load(shA + TEL, shB + TEL, BK);  cp_commit();

            const unsigned baseA = smem_u32(shA);
            const unsigned baseB = smem_u32(shB);
            int cst = 0, ldst = 2;
            for (int kt = 0; kt < nk; ++kt) {
                cp_wait<1>();
                __syncthreads();
                if (kt + 2 < nk) stage_load(shA + ldst * TEL, shB + ldst * TEL, (kt + 2) * BK);
                cp_commit();
                ldst = (ldst + 1 == 3) ? 0 : ldst + 1;
                const unsigned aS = baseA + (unsigned)(cst * TEL) * 2u;
                const unsigned bS = baseB + (unsigned)(cst * TEL) * 2u;
                cst = (cst + 1 == 3) ? 0 : cst + 1;
                #pragma unroll
                for (int kk = 0; kk < BK; kk += 16) {
                    unsigned af[4][4];
                    #pragma unroll
                    for (int mi = 0; mi < 4; mi++) {
                        int rrow = wm * 64 + mi * 16 + (lane & 15);
                        int rcol = kk + ((lane >> 4) << 3);
                        ldsm_x4(af[mi][0], af[mi][1], af[mi][2], af[mi][3],
                                aS + (unsigned)(rrow * LDS + rcol) * 2u);
                    }
                    unsigned bfr[4][2];
                    #pragma unroll
                    for (int njp = 0; njp < 2; njp++) {
                        unsigned r0, r1, r2, r3;
                        int rrow = wn * 32 + njp * 16 + (lane & 7) + ((lane >> 4) << 3);
                        int rcol = kk + (((lane >> 3) & 1) << 3);
                        ldsm_x4(r0, r1, r2, r3, bS + (unsigned)(rrow * LDS + rcol) * 2u);
                        bfr[njp * 2][0] = r0; bfr[njp * 2][1] = r1;
                        bfr[njp * 2 + 1][0] = r2; bfr[njp * 2 + 1][1] = r3;
                    }
                    #pragma unroll
                    for (int mi = 0; mi < 4; mi++)
                        #pragma unroll
                        for (int nj = 0; nj < 4; nj++)
                            mma16816(acc[mi][nj], af[mi], bfr[nj]);
                }
                __syncthreads();
            }

            #pragma unroll
            for (int mi = 0; mi < 4; mi++) {
                int mr0 = m0 + wm * 64 + mi * 16 + (lane >> 2);
                int mr1 = mr0 + 8;
                float rb0 = 0.f, rb1 = 0.f;
                if (EPI == 1 || EPI == 2) { rb0 = bias[mr0]; rb1 = bias[mr1]; }
                #pragma unroll
                for (int nj = 0; nj < 4; nj++) {
                    int nc = n0h + wn * 32 + nj * 8 + ((lane & 3) << 1);
                    float v0 = acc[mi][nj][0], v1 = acc[mi][nj][1];
                    float v2 = acc[mi][nj][2], v3 = acc[mi][nj][3];
                    if (EPI == 0) {
                        float c0 = bias[nc], c1 = bias[nc + 1];
                        *(unsigned *)(outH + coff + (size_t)mr0 * ldc + nc) = pack_bf16x2(v0 + c0, v1 + c1);
                        *(unsigned *)(outH + coff + (size_t)mr1 * ldc + nc) = pack_bf16x2(v2 + c0, v3 + c1);
                    } else if (EPI == 1) {
                        *(unsigned *)(outH + coff + (size_t)mr0 * ldc + nc) = pack_bf16x2(v0 + rb0, v1 + rb0);
                        *(unsigned *)(outH + coff + (size_t)mr1 * ldc + nc) = pack_bf16x2(v2 + rb1, v3 + rb1);
                    } else {
                        const float *rp = resid + coff;
                        float2 q0 = *(const float2 *)(rp + (size_t)mr0 * ldc + nc);
                        float2 q1 = *(const float2 *)(rp + (size_t)mr1 * ldc + nc);
                        *(float2 *)(outF + coff + (size_t)mr0 * ldc + nc) = make_float2(v0 + rb0 + q0.x, v1 + rb0 + q0.y);
                        *(float2 *)(outF + coff + (size_t)mr1 * ldc + nc) = make_float2(v2 + rb1 + q1.x, v3 + rb1 + q1.y);
                    }
                }
            }
            __syncthreads();
        }
    }
#endif
}

// ============================================================================
// FUSED ATTENTION: round-13 protocol with COARSER ring stages:
//   k: 2 stages x 32KB (2 chunks each), v: 2 stages x 32KB (2 tiles each, by kc)
//   -> half the mbarrier handshakes and fences per m-tile.
// ============================================================================
static constexpr int SQ_OFF   = 1024;
static constexpr int KRING    = SQ_OFF + 65536;       // 2 x 32KB
static constexpr int VRING    = KRING + 65536;        // 2 x 32KB
static constexpr int SP_OFF   = VRING + 65536;        // 197632
static constexpr int ATT_SMEM = SP_OFF + 32768;       // 230400

__global__ void __launch_bounds__(256)
attn_fused(const bf16 *__restrict__ qk, const bf16 *__restrict__ v,
           bf16 *__restrict__ attnOut) {
    extern __shared__ __align__(1024) char smem[];
    const int tid = threadIdx.x, wid = tid >> 5, lane = tid & 31;
    const int G = gridDim.x;
    const int t0 = blockIdx.x;
    const long long sQK = (long long)NTOK * 512;
    const long long sCN = (long long)C * NTOK;
    const long long sAT = (long long)NTOK * C;
    const int NW = BATCH * 32;

#if HAS_TC
    const unsigned sb = smem_u32(smem);
    #define QF_B    (sb + 8)
    #define QFREE_B (sb + 16)
    #define KFULL(j) (sb + 24 + 8 * (j))
    #define KFREE(j) (sb + 40 + 8 * (j))
    #define VFULL(j) (sb + 56 + 8 * (j))
    #define VFREE(j) (sb + 72 + 8 * (j))
    #define SDONE(b) (sb + 88 + 8 * (b))
    #define PCONV_B (sb + 104)
    #define PFREE_B (sb + 112)
    #define AFIN_B  (sb + 120)
    #define EPID_B  (sb + 128)

    if (tid == 0) {
        mbar_init(QF_B, 96); mbar_init(QFREE_B, 1);
        #pragma unroll
        for (int j = 0; j < 2; j++) {
            mbar_init(KFULL(j), 96); mbar_init(KFREE(j), 1);
            mbar_init(VFULL(j), 96); mbar_init(VFREE(j), 1);
            mbar_init(SDONE(j), 1);
        }
        mbar_init(PCONV_B, 128); mbar_init(PFREE_B, 1);
        mbar_init(AFIN_B, 1); mbar_init(EPID_B, 128);
    }
    if (wid == 0) tc_alloc(sb, 512);
    __syncthreads();
    const unsigned tmem = *(volatile unsigned *)smem;

    if (wid >= 5) {
        // ------------- producers -------------
        const int ptid = tid - 160;
        unsigned phK[2] = {1, 1}, phV[2] = {1, 1};
        unsigned phQFree = 1;
        for (int w = t0; w < NW; w += G) {
            int b = w >> 5, qt = w & 31;
            const bf16 *Qb = qk + (size_t)b * sQK + (size_t)(qt * 128) * 512;
            const bf16 *Kb = qk + (size_t)b * sQK + 256;
            const bf16 *Vb = v  + (size_t)b * sCN;
            mbar_wait(QFREE_B, phQFree); phQFree ^= 1;
            #pragma unroll 4
            for (int i = 0; i < 43; i++) {
                int g = i * 96 + ptid;
                if (g < 4096) {
                    int sub = g >> 10, u = g & 1023, r = u >> 3, cc = u & 7;
                    cp16(sb + SQ_OFF + sub * 16384 + SW128_SWZ((unsigned)(r * 128 + cc * 16)),
                         Qb + (size_t)r * 512 + sub * 64 + cc * 8);
                }
            }
            cp_arrive_noinc(QF_B);
            for (int mt = 0; mt < 32; mt++) {
                #pragma unroll
                for (int j = 0; j < 2; j++) {          // k stages: 2 chunks each
                    mbar_wait(KFREE(j), phK[j]); phK[j] ^= 1;
                    const bf16 *src = Kb + (size_t)(mt * 128) * 512 + 2 * j * 64;
                    #pragma unroll
                    for (int i = 0; i < 22; i++) {
                        int g = i * 96 + ptid;
                        if (g < 2048) {
                            int ch = g >> 10, u = g & 1023, r = u >> 3, cc = u & 7;
                            cp16(sb + KRING + j * 32768 + ch * 16384 +
                                     SW128_SWZ((unsigned)(r * 128 + cc * 16)),
                                 src + ch * 64 + (size_t)r * 512 + cc * 8);
                        }
                    }
                    cp_arrive_noinc(KFULL(j));
                }
                #pragma unroll
                for (int kc = 0; kc < 2; kc++) {       // v stages: 2 tiles each (nh 0,1)
                    mbar_wait(VFREE(kc), phV[kc]); phV[kc] ^= 1;
                    const bf16 *src = Vb + mt * 128 + kc * 64;
                    #pragma unroll
                    for (int i = 0; i < 22; i++) {
                        int g = i * 96 + ptid;
                        if (g < 2048) {
                            int nh = g >> 10, u = g & 1023, r = u >> 3, cc = u & 7;
                            cp16(sb + VRING + kc * 32768 + nh * 16384 +
                                     SW128_SWZ((unsigned)(r * 128 + cc * 16)),
                                 src + (size_t)(nh * 128 + r) * NTOK + cc * 8);
                        }
                    }
                    cp_arrive_noinc(VFULL(kc));
                }
            }
        }
    } else if (wid == 4) {
        // ------------- MMA issuer -------------
        unsigned phKF[2] = {0, 0}, phVF[2] = {0, 0};
        unsigned phPC = 0, phED = 1, phQF = 0;
        for (int w = t0; w < NW; w += G) {
            mbar_wait(QF_B, phQF); phQF ^= 1;
            auto issueS = [&](int mt) {
                unsigned sbt = tmem + ((mt & 1) ? 128u : 0u);
                #pragma unroll
                for (int j = 0; j < 2; j++) {
                    mbar_wait(KFULL(j), phKF[j]); phKF[j] ^= 1;
                    if (lane == 0) {
                        fence_proxy_async_cta();
                        tc_fence_after();
                        #pragma unroll
                        for (int h = 0; h < 2; h++) {
                            int ch = 2 * j + h;
                            uint64_t ad = mkdesc(sb + SQ_OFF + ch * 16384);
                            uint64_t bd = mkdesc(sb + KRING + j * 32768 + h * 16384);
                            #pragma unroll
                            for (int k = 0; k < 4; k++)
                                tc_mma_f16_ss(sbt, ad + 2 * k, bd + 2 * k, IDESC_128x128,
                                              (ch > 0) | (k > 0));
                        }
                        tc_commit(KFREE(j));
                    }
                }
                if (lane == 0) tc_commit(SDONE(mt & 1));
            };
            issueS(0);
            for (int mt = 0; mt < 32; mt++) {
                if (mt + 1 < 32) issueS(mt + 1);
                else if (lane == 0) tc_commit(QFREE_B);
                mbar_wait(PCONV_B, phPC); phPC ^= 1;
                if (mt == 0) { mbar_wait(EPID_B, phED); phED ^= 1; }
                #pragma unroll
                for (int kc = 0; kc < 2; kc++) {
                    mbar_wait(VFULL(kc), phVF[kc]); phVF[kc] ^= 1;
                    if (lane == 0) {
                        fence_proxy_async_cta();
                        tc_fence_after();
                        uint64_t ad = mkdesc(sb + SP_OFF + kc * 16384);
                        unsigned en0 = (mt > 0) | (kc > 0);
                        #pragma unroll
                        for (int nh = 0; nh < 2; nh++) {
                            uint64_t bd = mkdesc(sb + VRING + kc * 32768 + nh * 16384);
                            unsigned dD = tmem + 256 + nh * 128;
                            #pragma unroll
                            for (int k = 0; k < 4; k++)
                                tc_mma_f16_ss(dD, ad + 2 * k, bd + 2 * k, IDESC_128x128,
                                              en0 | (k > 0));
                        }
                        tc_commit(VFREE(kc));
                    }
                }
                if (lane == 0) {
                    tc_commit(PFREE_B);
                    if (mt == 31) tc_commit(AFIN_B);
                }
            }
        }
    } else {
        // ------------- epilogue (warps 0-3): round-13 conversion -------------
        unsigned phSD[2] = {0, 0};
        unsigned phPF = 1, phAF = 0;
        const int row = wid * 32 + lane;
        for (int w = t0; w < NW; w += G) {
            int b = w >> 5, qt = w & 31;
            const int gr = qt * 128 + row;
            float rsum = 0.f;
            for (int mt = 0; mt < 32; mt++) {
                const int sbz = mt & 1;
                mbar_wait(SDONE(sbz), phSD[sbz]); phSD[sbz] ^= 1;
                mbar_wait(PFREE_B, phPF); phPF ^= 1;
                tc_fence_after();
                const unsigned sbuf = tmem + (sbz ? 128u : 0u);
                #pragma unroll
                for (int g = 0; g < 4; g++) {
                    uint32_t r[32];
                    ldtm_x32(r, sbuf + g * 32);
                    tc_wait_ld();
                    #pragma unroll
                    for (int uu = 0; uu < 4; uu++) {
                        float e[8];
                        #pragma unroll
                        for (int j = 0; j < 8; j++) {
                            e[j] = __expf(__uint_as_float(r[uu * 8 + j]));
                            rsum += e[j];
                        }
                        uint4 pk = make_uint4(pack_bf16x2(e[0], e[1]), pack_bf16x2(e[2], e[3]),
                                              pack_bf16x2(e[4], e[5]), pack_bf16x2(e[6], e[7]));
                        int unit = g * 4 + uu;
                        int kc = unit >> 3, cc = unit & 7;
                        *(uint4 *)(smem + SP_OFF + kc * 16384 +
                                   SW128_SWZ((unsigned)(row * 128 + cc * 16))) = pk;
                    }
                }
                fence_proxy_async_cta();
                mbar_arrive(PCONV_B);
            }
            mbar_wait(AFIN_B, phAF); phAF ^= 1;
            tc_fence_after();
            const float scale = __frcp_rn(rsum);
            bf16 *orow = attnOut + (size_t)b * sAT + (size_t)gr * 256;
            #pragma unroll
            for (int g = 0; g < 8; g++) {
                uint32_t r[32];
                ldtm_x32(r, tmem + 256 + g * 32);
                tc_wait_ld();
                unsigned wpk[16];
                #pragma unroll
                for (int j = 0; j < 32; j += 2)
                    wpk[j >> 1] = pack_bf16x2(__uint_as_float(r[j]) * scale,
                                              __uint_as_float(r[j + 1]) * scale);
                uint4 *dst = (uint4 *)(orow + g * 32);
                #pragma unroll
                for (int qq = 0; qq < 4; qq++)
                    dst[qq] = make_uint4(wpk[4 * qq], wpk[4 * qq + 1], wpk[4 * qq + 2], wpk[4 * qq + 3]);
            }
            tc_fence_before();
            mbar_arrive(EPID_B);
        }
    }

    __syncthreads();
    if (wid == 0) { tc_relinq(); tc_dealloc(tmem, 512); }
    #undef QF_B
    #undef QFREE_B
    #undef KFULL
    #undef KFREE
    #undef VFULL
    #undef VFREE
    #undef SDONE
    #undef PCONV_B
    #undef PFREE_B
    #undef AFIN_B
    #undef EPID_B

#else
    // ---- slow-but-correct fallback (base-arch pass; never the loaded cubin) ----
    for (int w = t0; w < NW; w += G) {
        int b = w >> 5, qt = w & 31;
        const bf16 *Qb = qk + (size_t)b * sQK;
        const bf16 *Kb = qk + (size_t)b * sQK + 256;
        const bf16 *Vb = v  + (size_t)b * sCN;
        for (int rr = wid; rr < 128; rr += 8) {
            int n = qt * 128 + rr;
            float qreg[8];
            #pragma unroll
            for (int i = 0; i < 8; i++)
                qreg[i] = __bfloat162float(Qb[(size_t)n * 512 + lane * 8 + i]);
            float acc[8];
            #pragma unroll
            for (int i = 0; i < 8; i++) acc[i] = 0.f;
            float rsum = 0.f;
            for (int m = 0; m < NTOK; m++) {
                float s = 0.f;
                #pragma unroll
                for (int i = 0; i < 8; i++)
                    s += qreg[i] * __bfloat162float(Kb[(size_t)m * 512 + lane * 8 + i]);
                s = warp_sum(s);
                float p = __bfloat162float(__float2bfloat16(__expf(s)));
                if (lane == 0) rsum += p;
                #pragma unroll
                for (int i = 0; i < 8; i++)
                    acc[i] += p * __bfloat162float(Vb[(size_t)(lane * 8 + i) * NTOK + m]);
            }
            rsum = __shfl_sync(0xffffffffu, rsum, 0);
            float inv = 1.f / rsum;
            #pragma unroll
            for (int i = 0; i < 8; i++)
                attnOut[(size_t)b * sAT + (size_t)n * 256 + lane * 8 + i] =
                    __float2bfloat16(acc[i] * inv);
        }
    }
#endif
}

// ---------------- launch ----------------
extern "C" void kernel_launch(void *const *d_in, const int *in_sizes, int n_in,
                              void *d_out, int out_size) {
    const float *x   = (const float *)d_in[0];
    const float *gsc = (const float *)d_in[1];
    const float *gbi = (const float *)d_in[2];
    const float *wq  = (const float *)d_in[3];
    const float *bq  = (const float *)d_in[4];
    const float *wk  = (const float *)d_in[5];
    const float *bk  = (const float *)d_in[6];
    const float *wv  = (const float *)d_in[7];
    const float *bv  = (const float *)d_in[8];
    const float *wo  = (const float *)d_in[9];
    const float *bo  = (const float *)d_in[10];
    float *out = (float *)d_out;

    void *p_xn, *p_wqk, *p_wv, *p_wo, *p_bqk, *p_bv, *p_qk, *p_v, *p_attn;
    cudaGetSymbolAddress(&p_xn, g_xn);
    cudaGetSymbolAddress(&p_wqk, g_wqk);
    cudaGetSymbolAddress(&p_wv, g_wv);
    cudaGetSymbolAddress(&p_wo, g_wo);
    cudaGetSymbolAddress(&p_bqk, g_bqk);
    cudaGetSymbolAddress(&p_bv, g_bv);
    cudaGetSymbolAddress(&p_qk, g_qk);
    cudaGetSymbolAddress(&p_v, g_v);
    cudaGetSymbolAddress(&p_attn, g_attn);

    const long long sCN = (long long)C * NTOK;
    const long long sQK = (long long)NTOK * 512;
    const long long sAT = (long long)NTOK * C;

    cudaFuncSetAttribute(tc_gemm<0>, cudaFuncAttributeMaxDynamicSharedMemorySize, GEMM_SMEM);
    cudaFuncSetAttribute(tc_gemm<1>, cudaFuncAttributeMaxDynamicSharedMemorySize, GEMM_SMEM);
    cudaFuncSetAttribute(tc_gemm<2>, cudaFuncAttributeMaxDynamicSharedMemorySize, GEMM_SMEM);
    cudaFuncSetAttribute(attn_fused, cudaFuncAttributeMaxDynamicSharedMemorySize, ATT_SMEM);

    auto gsz = [](int T) { return T < 148 ? T : 148; };

    prep_weights<<<(4 * C * C + 3 * C + 255) / 256, 256>>>(wq, bq, wk, bk, wv, bv, wo);
    gn_stats_kernel<<<BATCH * GRP, 256>>>(x);
    gn_apply_t<<<dim3(NTOK / 32, C / 32, BATCH), 256>>>(x, gsc, gbi);

    // 1) qk_t[n, o] = xn_t[n,:] . wqk[o,:]  + bias[col o]
    tc_gemm<0><<<gsz(512), 256, GEMM_SMEM>>>(
        (const bf16 *)p_xn, (const bf16 *)p_wqk, C, C, C,
        sCN, 0LL, (const float *)p_bqk,
        (bf16 *)p_qk, nullptr, 512, sQK, nullptr, 2, 32, 512);

    // 2) v[o, m] = wv[o,:] . xn_t[m,:]  + bias[row o]
    tc_gemm<1><<<gsz(256), 256, GEMM_SMEM>>>(
        (const bf16 *)p_wv, (const bf16 *)p_xn, C, C, C,
        0LL, sCN, (const float *)p_bv,
        (bf16 *)p_v, nullptr, NTOK, sCN, nullptr, 16, 2, 256);

    // 3+4) fused attention -> g_attn (token-major [n][c], already /rowsum)
    attn_fused<<<gsz(256), 256, ATT_SMEM>>>(
        (const bf16 *)p_qk, (const bf16 *)p_v, (bf16 *)p_attn);

    // 5) out[o, n] = x[o, n] + wo[o,:] . attn_t[n,:] + bo[o]
    tc_gemm<2><<<gsz(256), 256, GEMM_SMEM>>>(
        (const bf16 *)p_wo, (const bf16 *)p_attn, C, C, C,
        0LL, sAT, bo,
        nullptr, out, NTOK, sCN, x, 16, 2, 256);
}